// round 11
// baseline (speedup 1.0000x reference)
#include <cuda_runtime.h>

#define N_NODES  100000
#define N_EDGES  1600000
#define HIDDEN   64
#define EMB      2
#define N_GRAPHS 64
#define NQ       (N_EDGES / 4)       // 400000 int4-quads

// -------- scratch (device globals; zero-initialized at load, self-cleaning) ----
__device__ float    g_deg[N_NODES];      // deg accumulator (zeroed by k_hh phase 1)
__device__ float    g_dinv[N_NODES];     // rsqrt(deg+1)
__device__ float    g_xd[N_NODES];       // x[n]*dinv[n]
__device__ float    g_t[N_NODES];        // layer-1 unscaled agg (seeded = xd)
__device__ float2   g_hhd[N_NODES];      // hh[n]*dinv[n]
__device__ float2   g_u[N_NODES];        // layer-2 unscaled agg (seeded = hhd)
__device__ float2   g_part[512];         // per-block {sum, sumsq} partials (k_hh)
__device__ float    g_pool[N_GRAPHS * 2];  // zeroed by finalize
__device__ float    g_cnt[N_GRAPHS];
__device__ unsigned g_done;              // agg2pool finalize counter
__device__ unsigned g_bar, g_bar2;       // k_hh grid barrier (self-resetting)
__device__ unsigned g_bar3;              // agg2pool grid barrier (self-resetting)

// K1: deg[d] += w   (4 edges/thread)
__global__ void k_deg(const int4* __restrict__ dst4, const float4* __restrict__ ew4) {
    int i = blockIdx.x * blockDim.x + threadIdx.x;
    if (i >= NQ) return;
    int4   d = __ldg(&dst4[i]);
    float4 w = __ldg(&ew4[i]);
    atomicAdd(&g_deg[d.x], w.x); atomicAdd(&g_deg[d.y], w.y);
    atomicAdd(&g_deg[d.z], w.z); atomicAdd(&g_deg[d.w], w.w);
}

// K2: dinv = rsqrt(deg+1); xd = x*dinv; seed t
__global__ void k_dinv(const float* __restrict__ x) {
    int n = blockIdx.x * blockDim.x + threadIdx.x;
    if (n >= N_NODES) return;
    float di = rsqrtf(g_deg[n] + 1.0f);
    float xd = __ldg(&x[n]) * di;
    g_dinv[n] = di;
    g_xd[n]   = xd;
    g_t[n]    = xd;                      // self-loop seed
}

// K3: t[d] += xd[s]*w   (4 edges/thread)
__global__ void k_agg1(const int4* __restrict__ src4, const int4* __restrict__ dst4,
                       const float4* __restrict__ ew4) {
    int i = blockIdx.x * blockDim.x + threadIdx.x;
    if (i >= NQ) return;
    int4   s = __ldg(&src4[i]);
    int4   d = __ldg(&dst4[i]);
    float4 w = __ldg(&ew4[i]);
    float x0 = g_xd[s.x], x1 = g_xd[s.y], x2 = g_xd[s.z], x3 = g_xd[s.w];
    atomicAdd(&g_t[d.x], x0 * w.x); atomicAdd(&g_t[d.y], x1 * w.y);
    atomicAdd(&g_t[d.z], x2 * w.z); atomicAdd(&g_t[d.w], x3 * w.w);
}

// K4 (fused reduce + bnconst + hh), hot-atomic-free:
//   Phase 1: block partial {sum,sumsq} -> g_part[blk] (distinct slots), arrive.
//   Grid barrier (391 blocks x 256 thr, all resident).
//   Phase 2: every block re-reduces the partials itself, computes S/T, does hh.
__global__ void __launch_bounds__(256) k_hh(const float* __restrict__ W1,
                                            const float* __restrict__ gamma,
                                            const float* __restrict__ beta,
                                            const float* __restrict__ W2,
                                            int nblocks) {
    __shared__ float  sS[HIDDEN], sT[HIDDEN], sW0[HIDDEN], sW1[HIDDEN];
    __shared__ float  ss[8], sq[8];
    __shared__ double sda[8], sdb[8];
    __shared__ double s_sum, s_sumsq;
    int tid = threadIdx.x, lane = tid & 31, wrp = tid >> 5;
    int n = blockIdx.x * blockDim.x + tid;
    bool valid = n < N_NODES;

    // ---- phase 1: block partial (keep di,t in registers for phase 2) ----
    float di = 0.f, t = 0.f, a = 0.f, b = 0.f;
    if (valid) {
        di = g_dinv[n];
        t  = g_t[n];
        float v = di * t;
        a = v; b = v * v;
        g_deg[n] = 0.0f;                 // self-clean for next graph replay
    }
#pragma unroll
    for (int o = 16; o; o >>= 1) {
        a += __shfl_down_sync(0xffffffffu, a, o);
        b += __shfl_down_sync(0xffffffffu, b, o);
    }
    if (lane == 0) { ss[wrp] = a; sq[wrp] = b; }
    __syncthreads();
    if (tid == 0) {
        a = ss[0] + ss[1] + ss[2] + ss[3] + ss[4] + ss[5] + ss[6] + ss[7];
        b = sq[0] + sq[1] + sq[2] + sq[3] + sq[4] + sq[5] + sq[6] + sq[7];
        g_part[blockIdx.x] = make_float2(a, b);   // distinct slot, no contention
        __threadfence();
        atomicAdd(&g_bar, 1u);
        while (*((volatile unsigned*)&g_bar) < (unsigned)nblocks)
            __nanosleep(32);
    }
    __syncthreads();

    // ---- every block reduces the partials (L2-hit loads, no atomics) ----
    double da = 0.0, db = 0.0;
    for (int k = tid; k < nblocks; k += 256) {
        float2 p = __ldcg(&g_part[k]);   // bypass L1 (written by other SMs)
        da += (double)p.x; db += (double)p.y;
    }
#pragma unroll
    for (int o = 16; o; o >>= 1) {
        da += __shfl_down_sync(0xffffffffu, da, o);
        db += __shfl_down_sync(0xffffffffu, db, o);
    }
    if (lane == 0) { sda[wrp] = da; sdb[wrp] = db; }
    __syncthreads();
    if (tid == 0) {
        s_sum   = sda[0] + sda[1] + sda[2] + sda[3] + sda[4] + sda[5] + sda[6] + sda[7];
        s_sumsq = sdb[0] + sdb[1] + sdb[2] + sdb[3] + sdb[4] + sdb[5] + sdb[6] + sdb[7];
    }
    __syncthreads();

    // ---- phase 2: bn constants + hh ----
    if (tid < HIDDEN) {
        float m   = (float)(s_sum / (double)N_NODES);
        float var = (float)(s_sumsq / (double)N_NODES) - m * m;
        float w   = __ldg(&W1[tid]);
        float inv = rsqrtf(var * w * w + 1e-5f);
        float sj  = w * inv * __ldg(&gamma[tid]);
        sS[tid] = sj;
        sT[tid] = __ldg(&beta[tid]) - m * sj;
        sW0[tid] = __ldg(&W2[tid * EMB + 0]);
        sW1[tid] = __ldg(&W2[tid * EMB + 1]);
    }
    __syncthreads();
    if (valid) {
        float av = di * t;
        float acc0 = 0.f, acc1 = 0.f;
#pragma unroll
        for (int j = 0; j < HIDDEN; j++) {
            float h = fmaxf(fmaf(av, sS[j], sT[j]), 0.0f);
            acc0 = fmaf(h, sW0[j], acc0);
            acc1 = fmaf(h, sW1[j], acc1);
        }
        float2 hhd = make_float2(acc0 * di, acc1 * di);
        g_hhd[n] = hhd;
        g_u[n]   = hhd;                  // self-loop seed for layer-2 agg
    }
    // ---- barrier self-reset (last exiting block) ----
    if (tid == 0) {
        unsigned v = atomicAdd(&g_bar2, 1u);
        if (v == (unsigned)(nblocks - 1)) { g_bar = 0u; g_bar2 = 0u; }
    }
}

// K5 (merged agg2 + pool), persistent 592 blocks x 256 (all resident):
//   Edge phase: u[d] += hhd[s]*w  (grid-stride over quads, float2 REDs)
//   Grid barrier.
//   Pool phase: warp-aggregated pool of dinv*u + counts; last block finalizes.
__global__ void __launch_bounds__(256) k_agg2pool(
        const int4* __restrict__ src4, const int4* __restrict__ dst4,
        const float4* __restrict__ ew4, const int* __restrict__ batch,
        const float* __restrict__ b2, float* __restrict__ out, int nblocks) {
    int tid = threadIdx.x;
    int gid = blockIdx.x * blockDim.x + tid;
    int gstride = nblocks * 256;

    // ---- edge phase ----
    for (int i = gid; i < NQ; i += gstride) {
        int4   s = __ldg(&src4[i]);
        int4   d = __ldg(&dst4[i]);
        float4 w = __ldg(&ew4[i]);
        float2 h0 = g_hhd[s.x], h1 = g_hhd[s.y], h2 = g_hhd[s.z], h3 = g_hhd[s.w];
        atomicAdd(&g_u[d.x], make_float2(h0.x * w.x, h0.y * w.x));
        atomicAdd(&g_u[d.y], make_float2(h1.x * w.y, h1.y * w.y));
        atomicAdd(&g_u[d.z], make_float2(h2.x * w.z, h2.y * w.z));
        atomicAdd(&g_u[d.w], make_float2(h3.x * w.w, h3.y * w.w));
    }
    // ---- grid barrier ----
    __syncthreads();
    if (tid == 0) {
        __threadfence();
        atomicAdd(&g_bar3, 1u);
        while (*((volatile unsigned*)&g_bar3) < (unsigned)nblocks)
            __nanosleep(32);
    }
    __syncthreads();

    // ---- pool phase (grid-stride keeps warp-contiguous node indices) ----
    for (int n = gid; n < N_NODES + (gstride - 1); n += gstride) {
        if (n - tid >= N_NODES) break;   // whole block past the end
        bool valid = n < N_NODES;
        int g = 0; float vx = 0.f, vy = 0.f, c = 0.f;
        if (valid) {
            g = __ldg(&batch[n]);
            float di = g_dinv[n];
            float2 u = __ldcg(&g_u[n]);
            vx = u.x * di; vy = u.y * di; c = 1.f;
        }
        int g0 = __shfl_sync(0xffffffffu, g, 0);
        bool uni = __all_sync(0xffffffffu, (g == g0) || !valid);
        if (uni) {
#pragma unroll
            for (int o = 16; o; o >>= 1) {
                vx += __shfl_down_sync(0xffffffffu, vx, o);
                vy += __shfl_down_sync(0xffffffffu, vy, o);
                c  += __shfl_down_sync(0xffffffffu, c,  o);
            }
            if ((tid & 31) == 0 && c > 0.f) {
                atomicAdd(&g_pool[g0 * 2 + 0], vx);
                atomicAdd(&g_pool[g0 * 2 + 1], vy);
                atomicAdd(&g_cnt[g0], c);
            }
        } else if (valid) {
            atomicAdd(&g_pool[g * 2 + 0], vx);
            atomicAdd(&g_pool[g * 2 + 1], vy);
            atomicAdd(&g_cnt[g], 1.0f);
        }
    }
    // ---- last-block finalize + self-clean (also resets g_bar3) ----
    __shared__ bool last;
    __threadfence();
    __syncthreads();
    if (tid == 0) last = (atomicAdd(&g_done, 1u) == (unsigned)(nblocks - 1));
    __syncthreads();
    if (last) {
        if (tid < N_GRAPHS) {
            float cc = fmaxf(g_cnt[tid], 1.0f);
            out[tid * 2 + 0] = g_pool[tid * 2 + 0] / cc + __ldg(&b2[0]);
            out[tid * 2 + 1] = g_pool[tid * 2 + 1] / cc + __ldg(&b2[1]);
            g_pool[tid * 2 + 0] = 0.0f;
            g_pool[tid * 2 + 1] = 0.0f;
            g_cnt[tid] = 0.0f;
        }
        if (tid == 0) { g_done = 0u; g_bar3 = 0u; }
    }
}

extern "C" void kernel_launch(void* const* d_in, const int* in_sizes, int n_in,
                              void* d_out, int out_size) {
    const float* x     = (const float*)d_in[0];
    const int*   ei    = (const int*)  d_in[1];   // [2, E]
    const float* ew    = (const float*)d_in[2];
    const int*   batch = (const int*)  d_in[3];
    const float* W1    = (const float*)d_in[4];
    const float* gamma = (const float*)d_in[6];
    const float* beta  = (const float*)d_in[7];
    const float* W2    = (const float*)d_in[8];
    const float* b2    = (const float*)d_in[9];
    float* out = (float*)d_out;

    const int4*   src4 = (const int4*)  ei;
    const int4*   dst4 = (const int4*) (ei + N_EDGES);
    const float4* ew4  = (const float4*) ew;

    const int BT  = 256;
    const int GN  = (N_NODES + BT - 1) / BT;    // 391 blocks (all-resident for k_hh barrier)
    const int GE4 = (NQ + BT - 1) / BT;
    const int GP  = 592;                        // agg2pool persistent blocks (all-resident)

    k_deg      <<<GE4, BT>>>(dst4, ew4);
    k_dinv     <<<GN, BT>>>(x);
    k_agg1     <<<GE4, BT>>>(src4, dst4, ew4);
    k_hh       <<<GN, BT>>>(W1, gamma, beta, W2, GN);
    k_agg2pool <<<GP, BT>>>(src4, dst4, ew4, batch, b2, out, GP);
}

// round 12
// speedup vs baseline: 1.0817x; 1.0817x over previous
#include <cuda_runtime.h>

#define N_NODES  100000
#define N_EDGES  1600000
#define HIDDEN   64
#define EMB      2
#define N_GRAPHS 64
#define NQ       (N_EDGES / 4)       // 400000 int4-quads
#define NN2      (N_NODES / 2)       // 50000 node-pairs

// -------- scratch (device globals; zero-initialized at load, self-cleaning) ----
__device__ float    g_deg[N_NODES];      // deg accumulator (zeroed by k_reduce)
__device__ float    g_dinv[N_NODES];     // rsqrt(deg+1)
__device__ float    g_xd[N_NODES];       // x[n]*dinv[n]
__device__ float    g_t[N_NODES];        // layer-1 unscaled agg (seeded = xd)
__device__ float2   g_hhd[N_NODES];      // hh[n]*dinv[n]
__device__ float2   g_u[N_NODES];        // layer-2 unscaled agg (seeded = hhd)
__device__ double   g_sum, g_sumsq;
__device__ float    g_pool[N_GRAPHS * 2];  // zeroed by k_pool last block
__device__ float    g_cnt[N_GRAPHS];
__device__ unsigned g_done;

// K1: deg[d] += w   (4 edges/thread; streaming loads keep L1 for scatter targets)
__global__ void k_deg(const int4* __restrict__ dst4, const float4* __restrict__ ew4) {
    int i = blockIdx.x * blockDim.x + threadIdx.x;
    if (i >= NQ) return;
    int4   d = __ldcs(&dst4[i]);
    float4 w = __ldcs(&ew4[i]);
    atomicAdd(&g_deg[d.x], w.x); atomicAdd(&g_deg[d.y], w.y);
    atomicAdd(&g_deg[d.z], w.z); atomicAdd(&g_deg[d.w], w.w);
}

// K2: dinv = rsqrt(deg+1); xd = x*dinv; seed t; zero bn sums
__global__ void k_dinv(const float* __restrict__ x) {
    int n = blockIdx.x * blockDim.x + threadIdx.x;
    if (n >= N_NODES) return;
    float di = rsqrtf(g_deg[n] + 1.0f);
    float xd = __ldg(&x[n]) * di;
    g_dinv[n] = di;
    g_xd[n]   = xd;
    g_t[n]    = xd;                      // self-loop seed
    if (n == 0) { g_sum = 0.0; g_sumsq = 0.0; }
}

// K3: t[d] += xd[s]*w   (4 edges/thread; edge arrays streamed, xd gathers cached)
__global__ void k_agg1(const int4* __restrict__ src4, const int4* __restrict__ dst4,
                       const float4* __restrict__ ew4) {
    int i = blockIdx.x * blockDim.x + threadIdx.x;
    if (i >= NQ) return;
    int4   s = __ldcs(&src4[i]);
    int4   d = __ldcs(&dst4[i]);
    float4 w = __ldcs(&ew4[i]);
    float x0 = g_xd[s.x], x1 = g_xd[s.y], x2 = g_xd[s.z], x3 = g_xd[s.w];
    atomicAdd(&g_t[d.x], x0 * w.x); atomicAdd(&g_t[d.y], x1 * w.y);
    atomicAdd(&g_t[d.z], x2 * w.z); atomicAdd(&g_t[d.w], x3 * w.w);
}

// K4: mean/var of a_n = dinv[n]*t[n] — float2/thread, 256-thread blocks.
//     Free-rides the g_deg self-clean (idle store bandwidth here).
__global__ void k_reduce() {
    __shared__ float ss[8], sq[8];
    int tid = threadIdx.x, lane = tid & 31, wrp = tid >> 5;
    int i = blockIdx.x * blockDim.x + tid;
    float a = 0.f, b = 0.f;
    if (i < NN2) {
        float2 t = __ldg(&((const float2*)g_t)[i]);
        float2 d = __ldg(&((const float2*)g_dinv)[i]);
        float v0 = d.x * t.x, v1 = d.y * t.y;
        a = v0 + v1;
        b = v0 * v0 + v1 * v1;
        ((float2*)g_deg)[i] = make_float2(0.0f, 0.0f);   // self-clean for next call
    }
#pragma unroll
    for (int o = 16; o; o >>= 1) {
        a += __shfl_down_sync(0xffffffffu, a, o);
        b += __shfl_down_sync(0xffffffffu, b, o);
    }
    if (lane == 0) { ss[wrp] = a; sq[wrp] = b; }
    __syncthreads();
    if (tid == 0) {
        a = ss[0] + ss[1] + ss[2] + ss[3] + ss[4] + ss[5] + ss[6] + ss[7];
        b = sq[0] + sq[1] + sq[2] + sq[3] + sq[4] + sq[5] + sq[6] + sq[7];
        atomicAdd(&g_sum,   (double)a);
        atomicAdd(&g_sumsq, (double)b);
    }
}

// K5: (bnconst fused) hhd[n] = (relu(a*S+T)@W2)*dinv ; seed u with hhd
__global__ void k_hh(const float* __restrict__ W1, const float* __restrict__ gamma,
                     const float* __restrict__ beta, const float* __restrict__ W2) {
    __shared__ float sS[HIDDEN], sT[HIDDEN], sW0[HIDDEN], sW1[HIDDEN];
    int tid = threadIdx.x;
    if (tid < HIDDEN) {
        float m   = (float)(g_sum / (double)N_NODES);
        float var = (float)(g_sumsq / (double)N_NODES) - m * m;
        float w   = __ldg(&W1[tid]);
        float inv = rsqrtf(var * w * w + 1e-5f);
        float sj  = w * inv * __ldg(&gamma[tid]);
        sS[tid] = sj;
        sT[tid] = __ldg(&beta[tid]) - m * sj;
        sW0[tid] = __ldg(&W2[tid * EMB + 0]);
        sW1[tid] = __ldg(&W2[tid * EMB + 1]);
    }
    __syncthreads();
    int n = blockIdx.x * blockDim.x + tid;
    if (n >= N_NODES) return;
    float di = g_dinv[n];
    float a  = di * g_t[n];
    float acc0 = 0.f, acc1 = 0.f;
#pragma unroll
    for (int j = 0; j < HIDDEN; j++) {
        float h = fmaxf(fmaf(a, sS[j], sT[j]), 0.0f);
        acc0 = fmaf(h, sW0[j], acc0);
        acc1 = fmaf(h, sW1[j], acc1);
    }
    float2 hhd = make_float2(acc0 * di, acc1 * di);
    g_hhd[n] = hhd;
    g_u[n]   = hhd;                      // self-loop seed for layer-2 agg
}

// K6: u[d] += hhd[s]*w   (4 edges/thread; edge arrays streamed, hhd gathers cached)
__global__ void k_agg2(const int4* __restrict__ src4, const int4* __restrict__ dst4,
                       const float4* __restrict__ ew4) {
    int i = blockIdx.x * blockDim.x + threadIdx.x;
    if (i >= NQ) return;
    int4   s = __ldcs(&src4[i]);
    int4   d = __ldcs(&dst4[i]);
    float4 w = __ldcs(&ew4[i]);
    float2 h0 = g_hhd[s.x], h1 = g_hhd[s.y], h2 = g_hhd[s.z], h3 = g_hhd[s.w];
    atomicAdd(&g_u[d.x], make_float2(h0.x * w.x, h0.y * w.x));
    atomicAdd(&g_u[d.y], make_float2(h1.x * w.y, h1.y * w.y));
    atomicAdd(&g_u[d.z], make_float2(h2.x * w.z, h2.y * w.z));
    atomicAdd(&g_u[d.w], make_float2(h3.x * w.w, h3.y * w.w));
}

// K7: pool out2[n] = dinv[n]*u[n] + counts (warp-aggregated),
//     last block finalizes output and self-cleans pool state.
__global__ void k_pool(const int* __restrict__ batch, const float* __restrict__ b2,
                       float* __restrict__ out, int nblocks) {
    int tid = threadIdx.x;
    int n = blockIdx.x * blockDim.x + tid;
    bool valid = n < N_NODES;
    int g = 0; float vx = 0.f, vy = 0.f, c = 0.f;
    if (valid) {
        g = __ldg(&batch[n]);
        float di = g_dinv[n];
        float2 u = g_u[n];
        vx = u.x * di; vy = u.y * di; c = 1.f;
    }
    // batch is sorted: warps almost always graph-uniform; lane 0 valid if any lane is
    int g0 = __shfl_sync(0xffffffffu, g, 0);
    bool uni = __all_sync(0xffffffffu, (g == g0) || !valid);
    if (uni) {
#pragma unroll
        for (int o = 16; o; o >>= 1) {
            vx += __shfl_down_sync(0xffffffffu, vx, o);
            vy += __shfl_down_sync(0xffffffffu, vy, o);
            c  += __shfl_down_sync(0xffffffffu, c,  o);
        }
        if ((tid & 31) == 0 && c > 0.f) {
            atomicAdd(&g_pool[g0 * 2 + 0], vx);
            atomicAdd(&g_pool[g0 * 2 + 1], vy);
            atomicAdd(&g_cnt[g0], c);
        }
    } else if (valid) {
        atomicAdd(&g_pool[g * 2 + 0], vx);
        atomicAdd(&g_pool[g * 2 + 1], vy);
        atomicAdd(&g_cnt[g], 1.0f);
    }
    // last-block finalize + self-clean
    __shared__ bool last;
    __threadfence();
    __syncthreads();
    if (tid == 0) last = (atomicAdd(&g_done, 1u) == (unsigned)(nblocks - 1));
    __syncthreads();
    if (last) {
        if (tid < N_GRAPHS) {
            float cc = fmaxf(g_cnt[tid], 1.0f);
            out[tid * 2 + 0] = g_pool[tid * 2 + 0] / cc + __ldg(&b2[0]);
            out[tid * 2 + 1] = g_pool[tid * 2 + 1] / cc + __ldg(&b2[1]);
            g_pool[tid * 2 + 0] = 0.0f;
            g_pool[tid * 2 + 1] = 0.0f;
            g_cnt[tid] = 0.0f;
        }
        if (tid == 0) g_done = 0u;
    }
}

extern "C" void kernel_launch(void* const* d_in, const int* in_sizes, int n_in,
                              void* d_out, int out_size) {
    const float* x     = (const float*)d_in[0];
    const int*   ei    = (const int*)  d_in[1];   // [2, E]
    const float* ew    = (const float*)d_in[2];
    const int*   batch = (const int*)  d_in[3];
    const float* W1    = (const float*)d_in[4];
    const float* gamma = (const float*)d_in[6];
    const float* beta  = (const float*)d_in[7];
    const float* W2    = (const float*)d_in[8];
    const float* b2    = (const float*)d_in[9];
    float* out = (float*)d_out;

    const int4*   src4 = (const int4*)  ei;
    const int4*   dst4 = (const int4*) (ei + N_EDGES);
    const float4* ew4  = (const float4*) ew;

    const int BT  = 256;
    const int GN  = (N_NODES + BT - 1) / BT;
    const int GE4 = (NQ + BT - 1) / BT;

    k_deg   <<<GE4, BT>>>(dst4, ew4);
    k_dinv  <<<GN, BT>>>(x);
    k_agg1  <<<GE4, BT>>>(src4, dst4, ew4);
    k_reduce<<<(NN2 + 255) / 256, 256>>>();
    k_hh    <<<GN, BT>>>(W1, gamma, beta, W2);
    k_agg2  <<<GE4, BT>>>(src4, dst4, ew4);
    k_pool  <<<GN, BT>>>(batch, b2, out, GN);
}

// round 14
// speedup vs baseline: 1.0829x; 1.0010x over previous
#include <cuda_runtime.h>

#define N_NODES  100000
#define N_EDGES  1600000
#define HIDDEN   64
#define EMB      2
#define N_GRAPHS 64
#define NQ       (N_EDGES / 4)       // 400000 int4-quads
#define NN2      (N_NODES / 2)       // 50000 node-pairs

// -------- scratch (device globals; zero-initialized at load, self-cleaning) ----
__device__ float    g_deg[N_NODES];      // deg accumulator (zeroed by k_reduce)
__device__ float    g_dinv[N_NODES];     // rsqrt(deg+1)
__device__ float    g_xd[N_NODES];       // x[n]*dinv[n]
__device__ float    g_t[N_NODES];        // layer-1 unscaled agg (seeded = xd)
__device__ float2   g_hhd[N_NODES];      // hh[n]*dinv[n]
__device__ float2   g_u[N_NODES];        // layer-2 edge-agg only (zeroed by k_reduce)
__device__ double   g_sum, g_sumsq;
__device__ float    g_pool[N_GRAPHS * 2];  // zeroed by k_pool last block
__device__ float    g_cnt[N_GRAPHS];
__device__ unsigned g_done;

// K1: deg[d] += w   (4 edges/thread)
__global__ void k_deg(const int4* __restrict__ dst4, const float4* __restrict__ ew4) {
    int i = blockIdx.x * blockDim.x + threadIdx.x;
    if (i >= NQ) return;
    int4   d = __ldg(&dst4[i]);
    float4 w = __ldg(&ew4[i]);
    atomicAdd(&g_deg[d.x], w.x); atomicAdd(&g_deg[d.y], w.y);
    atomicAdd(&g_deg[d.z], w.z); atomicAdd(&g_deg[d.w], w.w);
}

// K2: dinv = rsqrt(deg+1); xd = x*dinv; seed t; zero bn sums
__global__ void k_dinv(const float* __restrict__ x) {
    int n = blockIdx.x * blockDim.x + threadIdx.x;
    if (n >= N_NODES) return;
    float di = rsqrtf(g_deg[n] + 1.0f);
    float xd = __ldg(&x[n]) * di;
    g_dinv[n] = di;
    g_xd[n]   = xd;
    g_t[n]    = xd;                      // self-loop seed
    if (n == 0) { g_sum = 0.0; g_sumsq = 0.0; }
}

// K3: t[d] += xd[s]*w   (4 edges/thread)
__global__ void k_agg1(const int4* __restrict__ src4, const int4* __restrict__ dst4,
                       const float4* __restrict__ ew4) {
    int i = blockIdx.x * blockDim.x + threadIdx.x;
    if (i >= NQ) return;
    int4   s = __ldg(&src4[i]);
    int4   d = __ldg(&dst4[i]);
    float4 w = __ldg(&ew4[i]);
    float x0 = g_xd[s.x], x1 = g_xd[s.y], x2 = g_xd[s.z], x3 = g_xd[s.w];
    atomicAdd(&g_t[d.x], x0 * w.x); atomicAdd(&g_t[d.y], x1 * w.y);
    atomicAdd(&g_t[d.z], x2 * w.z); atomicAdd(&g_t[d.w], x3 * w.w);
}

// K4: mean/var of a_n = dinv[n]*t[n] — float2/thread.
//     Free-rides on idle store BW: cleans g_deg AND zeroes g_u for k_agg2.
__global__ void k_reduce() {
    __shared__ float ss[8], sq[8];
    int tid = threadIdx.x, lane = tid & 31, wrp = tid >> 5;
    int i = blockIdx.x * blockDim.x + tid;
    float a = 0.f, b = 0.f;
    if (i < NN2) {
        float2 t = __ldg(&((const float2*)g_t)[i]);
        float2 d = __ldg(&((const float2*)g_dinv)[i]);
        float v0 = d.x * t.x, v1 = d.y * t.y;
        a = v0 + v1;
        b = v0 * v0 + v1 * v1;
        ((float2*)g_deg)[i] = make_float2(0.0f, 0.0f);   // self-clean for next call
        ((float4*)g_u)[i]   = make_float4(0.0f, 0.0f, 0.0f, 0.0f); // zero 2 float2 slots
    }
#pragma unroll
    for (int o = 16; o; o >>= 1) {
        a += __shfl_down_sync(0xffffffffu, a, o);
        b += __shfl_down_sync(0xffffffffu, b, o);
    }
    if (lane == 0) { ss[wrp] = a; sq[wrp] = b; }
    __syncthreads();
    if (tid == 0) {
        a = ss[0] + ss[1] + ss[2] + ss[3] + ss[4] + ss[5] + ss[6] + ss[7];
        b = sq[0] + sq[1] + sq[2] + sq[3] + sq[4] + sq[5] + sq[6] + sq[7];
        atomicAdd(&g_sum,   (double)a);
        atomicAdd(&g_sumsq, (double)b);
    }
}

// K5: (bnconst fused) hhd[n] = (relu(a*S+T)@W2)*dinv  (single 800KB store)
__global__ void k_hh(const float* __restrict__ W1, const float* __restrict__ gamma,
                     const float* __restrict__ beta, const float* __restrict__ W2) {
    __shared__ float sS[HIDDEN], sT[HIDDEN], sW0[HIDDEN], sW1[HIDDEN];
    int tid = threadIdx.x;
    if (tid < HIDDEN) {
        float m   = (float)(g_sum / (double)N_NODES);
        float var = (float)(g_sumsq / (double)N_NODES) - m * m;
        float w   = __ldg(&W1[tid]);
        float inv = rsqrtf(var * w * w + 1e-5f);
        float sj  = w * inv * __ldg(&gamma[tid]);
        sS[tid] = sj;
        sT[tid] = __ldg(&beta[tid]) - m * sj;
        sW0[tid] = __ldg(&W2[tid * EMB + 0]);
        sW1[tid] = __ldg(&W2[tid * EMB + 1]);
    }
    __syncthreads();
    int n = blockIdx.x * blockDim.x + tid;
    if (n >= N_NODES) return;
    float di = g_dinv[n];
    float a  = di * g_t[n];
    float acc0 = 0.f, acc1 = 0.f;
#pragma unroll
    for (int j = 0; j < HIDDEN; j++) {
        float h = fmaxf(fmaf(a, sS[j], sT[j]), 0.0f);
        acc0 = fmaf(h, sW0[j], acc0);
        acc1 = fmaf(h, sW1[j], acc1);
    }
    g_hhd[n] = make_float2(acc0 * di, acc1 * di);
}

// K6: u[d] += hhd[s]*w   (4 edges/thread, float2 vector atomics; u pre-zeroed)
__global__ void k_agg2(const int4* __restrict__ src4, const int4* __restrict__ dst4,
                       const float4* __restrict__ ew4) {
    int i = blockIdx.x * blockDim.x + threadIdx.x;
    if (i >= NQ) return;
    int4   s = __ldg(&src4[i]);
    int4   d = __ldg(&dst4[i]);
    float4 w = __ldg(&ew4[i]);
    float2 h0 = g_hhd[s.x], h1 = g_hhd[s.y], h2 = g_hhd[s.z], h3 = g_hhd[s.w];
    atomicAdd(&g_u[d.x], make_float2(h0.x * w.x, h0.y * w.x));
    atomicAdd(&g_u[d.y], make_float2(h1.x * w.y, h1.y * w.y));
    atomicAdd(&g_u[d.z], make_float2(h2.x * w.z, h2.y * w.z));
    atomicAdd(&g_u[d.w], make_float2(h3.x * w.w, h3.y * w.w));
}

// K7: pool out2[n] = dinv[n]*(u[n] + hhd[n]) + counts (warp-aggregated),
//     last block finalizes output and self-cleans pool state.
//     (hhd[n] carries the self-loop term; u holds only the edge aggregation.)
__global__ void k_pool(const int* __restrict__ batch, const float* __restrict__ b2,
                       float* __restrict__ out, int nblocks) {
    int tid = threadIdx.x;
    int n = blockIdx.x * blockDim.x + tid;
    bool valid = n < N_NODES;
    int g = 0; float vx = 0.f, vy = 0.f, c = 0.f;
    if (valid) {
        g = __ldg(&batch[n]);
        float di = g_dinv[n];
        float2 u = g_u[n];
        float2 h = g_hhd[n];
        vx = (u.x + h.x) * di; vy = (u.y + h.y) * di; c = 1.f;
    }
    // batch is sorted: warps almost always graph-uniform; lane 0 valid if any lane is
    int g0 = __shfl_sync(0xffffffffu, g, 0);
    bool uni = __all_sync(0xffffffffu, (g == g0) || !valid);
    if (uni) {
#pragma unroll
        for (int o = 16; o; o >>= 1) {
            vx += __shfl_down_sync(0xffffffffu, vx, o);
            vy += __shfl_down_sync(0xffffffffu, vy, o);
            c  += __shfl_down_sync(0xffffffffu, c,  o);
        }
        if ((tid & 31) == 0 && c > 0.f) {
            atomicAdd(&g_pool[g0 * 2 + 0], vx);
            atomicAdd(&g_pool[g0 * 2 + 1], vy);
            atomicAdd(&g_cnt[g0], c);
        }
    } else if (valid) {
        atomicAdd(&g_pool[g * 2 + 0], vx);
        atomicAdd(&g_pool[g * 2 + 1], vy);
        atomicAdd(&g_cnt[g], 1.0f);
    }
    // last-block finalize + self-clean
    __shared__ bool last;
    __threadfence();
    __syncthreads();
    if (tid == 0) last = (atomicAdd(&g_done, 1u) == (unsigned)(nblocks - 1));
    __syncthreads();
    if (last) {
        if (tid < N_GRAPHS) {
            float cc = fmaxf(g_cnt[tid], 1.0f);
            out[tid * 2 + 0] = g_pool[tid * 2 + 0] / cc + __ldg(&b2[0]);
            out[tid * 2 + 1] = g_pool[tid * 2 + 1] / cc + __ldg(&b2[1]);
            g_pool[tid * 2 + 0] = 0.0f;
            g_pool[tid * 2 + 1] = 0.0f;
            g_cnt[tid] = 0.0f;
        }
        if (tid == 0) g_done = 0u;
    }
}

extern "C" void kernel_launch(void* const* d_in, const int* in_sizes, int n_in,
                              void* d_out, int out_size) {
    const float* x     = (const float*)d_in[0];
    const int*   ei    = (const int*)  d_in[1];   // [2, E]
    const float* ew    = (const float*)d_in[2];
    const int*   batch = (const int*)  d_in[3];
    const float* W1    = (const float*)d_in[4];
    const float* gamma = (const float*)d_in[6];
    const float* beta  = (const float*)d_in[7];
    const float* W2    = (const float*)d_in[8];
    const float* b2    = (const float*)d_in[9];
    float* out = (float*)d_out;

    const int4*   src4 = (const int4*)  ei;
    const int4*   dst4 = (const int4*) (ei + N_EDGES);
    const float4* ew4  = (const float4*) ew;

    const int BT  = 256;
    const int GN  = (N_NODES + BT - 1) / BT;
    const int GE4 = (NQ + BT - 1) / BT;

    k_deg   <<<GE4, BT>>>(dst4, ew4);
    k_dinv  <<<GN, BT>>>(x);
    k_agg1  <<<GE4, BT>>>(src4, dst4, ew4);
    k_reduce<<<(NN2 + 255) / 256, 256>>>();
    k_hh    <<<GN, BT>>>(W1, gamma, beta, W2);
    k_agg2  <<<GE4, BT>>>(src4, dst4, ew4);
    k_pool  <<<GN, BT>>>(batch, b2, out, GN);
}

// round 15
// speedup vs baseline: 1.1525x; 1.0643x over previous
#include <cuda_runtime.h>

#define N_NODES  100000
#define N_EDGES  1600000
#define HIDDEN   64
#define EMB      2
#define N_GRAPHS 64
#define NQ       (N_EDGES / 4)       // 400000 int4-quads
#define NN2      (N_NODES / 2)       // 50000 node-pairs

// -------- scratch (device globals; zero-initialized at load, self-cleaning) ----
__device__ float    g_deg[N_NODES];      // deg accumulator (zeroed by k_reduce)
__device__ float    g_dinv[N_NODES];     // rsqrt(deg+1)
__device__ float    g_xd[N_NODES];       // x[n]*dinv[n]
__device__ float    g_t[N_NODES];        // layer-1 unscaled agg (seeded = xd)
__device__ float2   g_hhd[N_NODES];      // hh[n]*dinv[n]
__device__ float2   g_u[N_NODES];        // layer-2 edge-agg only (zeroed by k_reduce)
__device__ double   g_sum, g_sumsq;
__device__ float    g_pool[N_GRAPHS * 2];  // zeroed by k_pool last block
__device__ float    g_cnt[N_GRAPHS];
__device__ unsigned g_done;

// K1: deg[d] += w.  Prefetch edge quads pre-sync (pure inputs); atomics post-sync
//     (g_deg zeroed by previous replay's k_reduce).
__global__ void k_deg(const int4* __restrict__ dst4, const float4* __restrict__ ew4) {
    int i = blockIdx.x * blockDim.x + threadIdx.x;
    bool act = i < NQ;
    int4 d; float4 w;
    if (act) { d = __ldg(&dst4[i]); w = __ldg(&ew4[i]); }
    cudaGridDependencySynchronize();
    if (act) {
        atomicAdd(&g_deg[d.x], w.x); atomicAdd(&g_deg[d.y], w.y);
        atomicAdd(&g_deg[d.z], w.z); atomicAdd(&g_deg[d.w], w.w);
    }
}

// K2: dinv = rsqrt(deg+1); xd = x*dinv; seed t; zero bn sums
__global__ void k_dinv(const float* __restrict__ x) {
    int n = blockIdx.x * blockDim.x + threadIdx.x;
    bool act = n < N_NODES;
    float xv = 0.f;
    if (act) xv = __ldg(&x[n]);          // pure input, prefetch pre-sync
    cudaGridDependencySynchronize();
    if (!act) return;
    float di = rsqrtf(g_deg[n] + 1.0f);
    float xd = xv * di;
    g_dinv[n] = di;
    g_xd[n]   = xd;
    g_t[n]    = xd;                      // self-loop seed
    if (n == 0) { g_sum = 0.0; g_sumsq = 0.0; }
}

// K3: t[d] += xd[s]*w
__global__ void k_agg1(const int4* __restrict__ src4, const int4* __restrict__ dst4,
                       const float4* __restrict__ ew4) {
    int i = blockIdx.x * blockDim.x + threadIdx.x;
    bool act = i < NQ;
    int4 s, d; float4 w;
    if (act) { s = __ldg(&src4[i]); d = __ldg(&dst4[i]); w = __ldg(&ew4[i]); }
    cudaGridDependencySynchronize();
    if (!act) return;
    float x0 = g_xd[s.x], x1 = g_xd[s.y], x2 = g_xd[s.z], x3 = g_xd[s.w];
    atomicAdd(&g_t[d.x], x0 * w.x); atomicAdd(&g_t[d.y], x1 * w.y);
    atomicAdd(&g_t[d.z], x2 * w.z); atomicAdd(&g_t[d.w], x3 * w.w);
}

// K4: mean/var of a_n = dinv[n]*t[n] — float2/thread.
//     Free-rides on idle store BW: cleans g_deg AND zeroes g_u for k_agg2.
__global__ void k_reduce() {
    __shared__ float ss[8], sq[8];
    int tid = threadIdx.x, lane = tid & 31, wrp = tid >> 5;
    int i = blockIdx.x * blockDim.x + tid;
    cudaGridDependencySynchronize();
    float a = 0.f, b = 0.f;
    if (i < NN2) {
        float2 t = __ldg(&((const float2*)g_t)[i]);
        float2 d = __ldg(&((const float2*)g_dinv)[i]);
        float v0 = d.x * t.x, v1 = d.y * t.y;
        a = v0 + v1;
        b = v0 * v0 + v1 * v1;
        ((float2*)g_deg)[i] = make_float2(0.0f, 0.0f);   // self-clean for next call
        ((float4*)g_u)[i]   = make_float4(0.0f, 0.0f, 0.0f, 0.0f); // zero 2 float2 slots
    }
#pragma unroll
    for (int o = 16; o; o >>= 1) {
        a += __shfl_down_sync(0xffffffffu, a, o);
        b += __shfl_down_sync(0xffffffffu, b, o);
    }
    if (lane == 0) { ss[wrp] = a; sq[wrp] = b; }
    __syncthreads();
    if (tid == 0) {
        a = ss[0] + ss[1] + ss[2] + ss[3] + ss[4] + ss[5] + ss[6] + ss[7];
        b = sq[0] + sq[1] + sq[2] + sq[3] + sq[4] + sq[5] + sq[6] + sq[7];
        atomicAdd(&g_sum,   (double)a);
        atomicAdd(&g_sumsq, (double)b);
    }
}

// K5: (bnconst fused) hhd[n] = (relu(a*S+T)@W2)*dinv  (single 800KB store)
__global__ void k_hh(const float* __restrict__ W1, const float* __restrict__ gamma,
                     const float* __restrict__ beta, const float* __restrict__ W2) {
    __shared__ float sS[HIDDEN], sT[HIDDEN], sW0[HIDDEN], sW1[HIDDEN];
    int tid = threadIdx.x;
    float w = 0.f, ga = 0.f, be = 0.f, w20 = 0.f, w21 = 0.f;
    if (tid < HIDDEN) {                  // pure inputs, prefetch pre-sync
        w   = __ldg(&W1[tid]);
        ga  = __ldg(&gamma[tid]);
        be  = __ldg(&beta[tid]);
        w20 = __ldg(&W2[tid * EMB + 0]);
        w21 = __ldg(&W2[tid * EMB + 1]);
    }
    cudaGridDependencySynchronize();
    if (tid < HIDDEN) {
        float m   = (float)(g_sum / (double)N_NODES);
        float var = (float)(g_sumsq / (double)N_NODES) - m * m;
        float inv = rsqrtf(var * w * w + 1e-5f);
        float sj  = w * inv * ga;
        sS[tid] = sj;
        sT[tid] = be - m * sj;
        sW0[tid] = w20;
        sW1[tid] = w21;
    }
    __syncthreads();
    int n = blockIdx.x * blockDim.x + tid;
    if (n >= N_NODES) return;
    float di = g_dinv[n];
    float a  = di * g_t[n];
    float acc0 = 0.f, acc1 = 0.f;
#pragma unroll
    for (int j = 0; j < HIDDEN; j++) {
        float h = fmaxf(fmaf(a, sS[j], sT[j]), 0.0f);
        acc0 = fmaf(h, sW0[j], acc0);
        acc1 = fmaf(h, sW1[j], acc1);
    }
    g_hhd[n] = make_float2(acc0 * di, acc1 * di);
}

// K6: u[d] += hhd[s]*w   (float2 vector atomics; u pre-zeroed by k_reduce)
__global__ void k_agg2(const int4* __restrict__ src4, const int4* __restrict__ dst4,
                       const float4* __restrict__ ew4) {
    int i = blockIdx.x * blockDim.x + threadIdx.x;
    bool act = i < NQ;
    int4 s, d; float4 w;
    if (act) { s = __ldg(&src4[i]); d = __ldg(&dst4[i]); w = __ldg(&ew4[i]); }
    cudaGridDependencySynchronize();
    if (!act) return;
    float2 h0 = g_hhd[s.x], h1 = g_hhd[s.y], h2 = g_hhd[s.z], h3 = g_hhd[s.w];
    atomicAdd(&g_u[d.x], make_float2(h0.x * w.x, h0.y * w.x));
    atomicAdd(&g_u[d.y], make_float2(h1.x * w.y, h1.y * w.y));
    atomicAdd(&g_u[d.z], make_float2(h2.x * w.z, h2.y * w.z));
    atomicAdd(&g_u[d.w], make_float2(h3.x * w.w, h3.y * w.w));
}

// K7: pool out2[n] = dinv[n]*(u[n] + hhd[n]) + counts (warp-aggregated),
//     last block finalizes output and self-cleans pool state.
__global__ void k_pool(const int* __restrict__ batch, const float* __restrict__ b2,
                       float* __restrict__ out, int nblocks) {
    int tid = threadIdx.x;
    int n = blockIdx.x * blockDim.x + tid;
    bool valid = n < N_NODES;
    int g = 0;
    if (valid) g = __ldg(&batch[n]);     // pure input, prefetch pre-sync
    cudaGridDependencySynchronize();
    float vx = 0.f, vy = 0.f, c = 0.f;
    if (valid) {
        float di = g_dinv[n];
        float2 u = g_u[n];
        float2 h = g_hhd[n];
        vx = (u.x + h.x) * di; vy = (u.y + h.y) * di; c = 1.f;
    }
    // batch is sorted: warps almost always graph-uniform; lane 0 valid if any lane is
    int g0 = __shfl_sync(0xffffffffu, g, 0);
    bool uni = __all_sync(0xffffffffu, (g == g0) || !valid);
    if (uni) {
#pragma unroll
        for (int o = 16; o; o >>= 1) {
            vx += __shfl_down_sync(0xffffffffu, vx, o);
            vy += __shfl_down_sync(0xffffffffu, vy, o);
            c  += __shfl_down_sync(0xffffffffu, c,  o);
        }
        if ((tid & 31) == 0 && c > 0.f) {
            atomicAdd(&g_pool[g0 * 2 + 0], vx);
            atomicAdd(&g_pool[g0 * 2 + 1], vy);
            atomicAdd(&g_cnt[g0], c);
        }
    } else if (valid) {
        atomicAdd(&g_pool[g * 2 + 0], vx);
        atomicAdd(&g_pool[g * 2 + 1], vy);
        atomicAdd(&g_cnt[g], 1.0f);
    }
    // last-block finalize + self-clean
    __shared__ bool last;
    __threadfence();
    __syncthreads();
    if (tid == 0) last = (atomicAdd(&g_done, 1u) == (unsigned)(nblocks - 1));
    __syncthreads();
    if (last) {
        if (tid < N_GRAPHS) {
            float cc = fmaxf(g_cnt[tid], 1.0f);
            out[tid * 2 + 0] = g_pool[tid * 2 + 0] / cc + __ldg(&b2[0]);
            out[tid * 2 + 1] = g_pool[tid * 2 + 1] / cc + __ldg(&b2[1]);
            g_pool[tid * 2 + 0] = 0.0f;
            g_pool[tid * 2 + 1] = 0.0f;
            g_cnt[tid] = 0.0f;
        }
        if (tid == 0) g_done = 0u;
    }
}

// ---- PDL launcher: overlap each kernel's ramp with predecessor's tail ----
static void launch_pdl(const void* func, int grid, int block, void** args) {
    cudaLaunchConfig_t cfg = {};
    cfg.gridDim  = dim3(grid, 1, 1);
    cfg.blockDim = dim3(block, 1, 1);
    cudaLaunchAttribute attr[1];
    attr[0].id = cudaLaunchAttributeProgrammaticStreamSerialization;
    attr[0].val.programmaticStreamSerializationAllowed = 1;
    cfg.attrs = attr;
    cfg.numAttrs = 1;
    cudaLaunchKernelExC(&cfg, func, args);
}

extern "C" void kernel_launch(void* const* d_in, const int* in_sizes, int n_in,
                              void* d_out, int out_size) {
    const float* x     = (const float*)d_in[0];
    const int*   ei    = (const int*)  d_in[1];   // [2, E]
    const float* ew    = (const float*)d_in[2];
    const int*   batch = (const int*)  d_in[3];
    const float* W1    = (const float*)d_in[4];
    const float* gamma = (const float*)d_in[6];
    const float* beta  = (const float*)d_in[7];
    const float* W2    = (const float*)d_in[8];
    const float* b2    = (const float*)d_in[9];
    float* out = (float*)d_out;

    const int4*   src4 = (const int4*)  ei;
    const int4*   dst4 = (const int4*) (ei + N_EDGES);
    const float4* ew4  = (const float4*) ew;

    const int BT  = 256;
    const int GN  = (N_NODES + BT - 1) / BT;
    const int GE4 = (NQ + BT - 1) / BT;
    const int GR  = (NN2 + 255) / 256;

    { void* a[] = { (void*)&dst4, (void*)&ew4 };
      launch_pdl((const void*)k_deg, GE4, BT, a); }
    { void* a[] = { (void*)&x };
      launch_pdl((const void*)k_dinv, GN, BT, a); }
    { void* a[] = { (void*)&src4, (void*)&dst4, (void*)&ew4 };
      launch_pdl((const void*)k_agg1, GE4, BT, a); }
    { void* a[] = {};
      launch_pdl((const void*)k_reduce, GR, 256, nullptr); (void)a; }
    { void* a[] = { (void*)&W1, (void*)&gamma, (void*)&beta, (void*)&W2 };
      launch_pdl((const void*)k_hh, GN, BT, a); }
    { void* a[] = { (void*)&src4, (void*)&dst4, (void*)&ew4 };
      launch_pdl((const void*)k_agg2, GE4, BT, a); }
    { int gn = GN;
      void* a[] = { (void*)&batch, (void*)&b2, (void*)&out, (void*)&gn };
      launch_pdl((const void*)k_pool, GN, BT, a); }
}

// round 16
// speedup vs baseline: 1.1590x; 1.0056x over previous
#include <cuda_runtime.h>

#define N_NODES  100000
#define N_EDGES  1600000
#define HIDDEN   64
#define EMB      2
#define N_GRAPHS 64
#define NQ       (N_EDGES / 4)       // 400000 int4-quads
#define NN2      (N_NODES / 2)       // 50000 node-pairs
#define EBLOCKS  1184                // 148 SMs x 8 blocks: exactly one wave
#define ESTRIDE  (EBLOCKS * 256)     // 303104 threads

// -------- scratch (device globals; zero-initialized at load, self-cleaning) ----
__device__ float    g_deg[N_NODES];      // deg accumulator (zeroed by k_reduce)
__device__ float    g_dinv[N_NODES];     // rsqrt(deg+1)
__device__ float    g_xd[N_NODES];       // x[n]*dinv[n]
__device__ float    g_t[N_NODES];        // layer-1 unscaled agg (seeded = xd)
__device__ float2   g_hhd[N_NODES];      // hh[n]*dinv[n]
__device__ float2   g_u[N_NODES];        // layer-2 edge-agg only (zeroed by k_reduce)
__device__ double   g_sum, g_sumsq;
__device__ float    g_pool[N_GRAPHS * 2];  // zeroed by k_pool last block
__device__ float    g_cnt[N_GRAPHS];
__device__ unsigned g_done;

// K1: deg[d] += w.  One-wave grid, 1-2 quads/thread, all prefetched pre-sync.
__global__ void __launch_bounds__(256) k_deg(const int4* __restrict__ dst4,
                                             const float4* __restrict__ ew4) {
    int i0 = blockIdx.x * blockDim.x + threadIdx.x;   // always < NQ
    int i1 = i0 + ESTRIDE;
    bool a1 = i1 < NQ;
    int4   d0 = __ldg(&dst4[i0]);
    float4 w0 = __ldg(&ew4[i0]);
    int4 d1; float4 w1;
    if (a1) { d1 = __ldg(&dst4[i1]); w1 = __ldg(&ew4[i1]); }
    cudaGridDependencySynchronize();
    atomicAdd(&g_deg[d0.x], w0.x); atomicAdd(&g_deg[d0.y], w0.y);
    atomicAdd(&g_deg[d0.z], w0.z); atomicAdd(&g_deg[d0.w], w0.w);
    if (a1) {
        atomicAdd(&g_deg[d1.x], w1.x); atomicAdd(&g_deg[d1.y], w1.y);
        atomicAdd(&g_deg[d1.z], w1.z); atomicAdd(&g_deg[d1.w], w1.w);
    }
}

// K2: dinv = rsqrt(deg+1); xd = x*dinv; seed t; zero bn sums
__global__ void k_dinv(const float* __restrict__ x) {
    int n = blockIdx.x * blockDim.x + threadIdx.x;
    bool act = n < N_NODES;
    float xv = 0.f;
    if (act) xv = __ldg(&x[n]);          // pure input, prefetch pre-sync
    cudaGridDependencySynchronize();
    if (!act) return;
    float di = rsqrtf(g_deg[n] + 1.0f);
    float xd = xv * di;
    g_dinv[n] = di;
    g_xd[n]   = xd;
    g_t[n]    = xd;                      // self-loop seed
    if (n == 0) { g_sum = 0.0; g_sumsq = 0.0; }
}

// K3: t[d] += xd[s]*w.  One-wave grid, 1-2 quads/thread prefetched pre-sync.
__global__ void __launch_bounds__(256) k_agg1(const int4* __restrict__ src4,
                                              const int4* __restrict__ dst4,
                                              const float4* __restrict__ ew4) {
    int i0 = blockIdx.x * blockDim.x + threadIdx.x;   // always < NQ
    int i1 = i0 + ESTRIDE;
    bool a1 = i1 < NQ;
    int4   s0 = __ldg(&src4[i0]);
    int4   d0 = __ldg(&dst4[i0]);
    float4 w0 = __ldg(&ew4[i0]);
    int4 s1, d1; float4 w1;
    if (a1) { s1 = __ldg(&src4[i1]); d1 = __ldg(&dst4[i1]); w1 = __ldg(&ew4[i1]); }
    cudaGridDependencySynchronize();
    float x0 = g_xd[s0.x], x1 = g_xd[s0.y], x2 = g_xd[s0.z], x3 = g_xd[s0.w];
    float x4, x5, x6, x7;
    if (a1) { x4 = g_xd[s1.x]; x5 = g_xd[s1.y]; x6 = g_xd[s1.z]; x7 = g_xd[s1.w]; }
    atomicAdd(&g_t[d0.x], x0 * w0.x); atomicAdd(&g_t[d0.y], x1 * w0.y);
    atomicAdd(&g_t[d0.z], x2 * w0.z); atomicAdd(&g_t[d0.w], x3 * w0.w);
    if (a1) {
        atomicAdd(&g_t[d1.x], x4 * w1.x); atomicAdd(&g_t[d1.y], x5 * w1.y);
        atomicAdd(&g_t[d1.z], x6 * w1.z); atomicAdd(&g_t[d1.w], x7 * w1.w);
    }
}

// K4: mean/var of a_n = dinv[n]*t[n] — float2/thread.
//     Free-rides on idle store BW: cleans g_deg AND zeroes g_u for k_agg2.
__global__ void k_reduce() {
    __shared__ float ss[8], sq[8];
    int tid = threadIdx.x, lane = tid & 31, wrp = tid >> 5;
    int i = blockIdx.x * blockDim.x + tid;
    cudaGridDependencySynchronize();
    float a = 0.f, b = 0.f;
    if (i < NN2) {
        float2 t = __ldg(&((const float2*)g_t)[i]);
        float2 d = __ldg(&((const float2*)g_dinv)[i]);
        float v0 = d.x * t.x, v1 = d.y * t.y;
        a = v0 + v1;
        b = v0 * v0 + v1 * v1;
        ((float2*)g_deg)[i] = make_float2(0.0f, 0.0f);   // self-clean for next call
        ((float4*)g_u)[i]   = make_float4(0.0f, 0.0f, 0.0f, 0.0f); // zero 2 float2 slots
    }
#pragma unroll
    for (int o = 16; o; o >>= 1) {
        a += __shfl_down_sync(0xffffffffu, a, o);
        b += __shfl_down_sync(0xffffffffu, b, o);
    }
    if (lane == 0) { ss[wrp] = a; sq[wrp] = b; }
    __syncthreads();
    if (tid == 0) {
        a = ss[0] + ss[1] + ss[2] + ss[3] + ss[4] + ss[5] + ss[6] + ss[7];
        b = sq[0] + sq[1] + sq[2] + sq[3] + sq[4] + sq[5] + sq[6] + sq[7];
        atomicAdd(&g_sum,   (double)a);
        atomicAdd(&g_sumsq, (double)b);
    }
}

// K5: (bnconst fused) hhd[n] = (relu(a*S+T)@W2)*dinv  (single 800KB store)
__global__ void k_hh(const float* __restrict__ W1, const float* __restrict__ gamma,
                     const float* __restrict__ beta, const float* __restrict__ W2) {
    __shared__ float sS[HIDDEN], sT[HIDDEN], sW0[HIDDEN], sW1[HIDDEN];
    int tid = threadIdx.x;
    float w = 0.f, ga = 0.f, be = 0.f, w20 = 0.f, w21 = 0.f;
    if (tid < HIDDEN) {                  // pure inputs, prefetch pre-sync
        w   = __ldg(&W1[tid]);
        ga  = __ldg(&gamma[tid]);
        be  = __ldg(&beta[tid]);
        w20 = __ldg(&W2[tid * EMB + 0]);
        w21 = __ldg(&W2[tid * EMB + 1]);
    }
    cudaGridDependencySynchronize();
    if (tid < HIDDEN) {
        float m   = (float)(g_sum / (double)N_NODES);
        float var = (float)(g_sumsq / (double)N_NODES) - m * m;
        float inv = rsqrtf(var * w * w + 1e-5f);
        float sj  = w * inv * ga;
        sS[tid] = sj;
        sT[tid] = be - m * sj;
        sW0[tid] = w20;
        sW1[tid] = w21;
    }
    __syncthreads();
    int n = blockIdx.x * blockDim.x + tid;
    if (n >= N_NODES) return;
    float di = g_dinv[n];
    float a  = di * g_t[n];
    float acc0 = 0.f, acc1 = 0.f;
#pragma unroll
    for (int j = 0; j < HIDDEN; j++) {
        float h = fmaxf(fmaf(a, sS[j], sT[j]), 0.0f);
        acc0 = fmaf(h, sW0[j], acc0);
        acc1 = fmaf(h, sW1[j], acc1);
    }
    g_hhd[n] = make_float2(acc0 * di, acc1 * di);
}

// K6: u[d] += hhd[s]*w.  One-wave grid, 1-2 quads/thread prefetched pre-sync.
__global__ void __launch_bounds__(256) k_agg2(const int4* __restrict__ src4,
                                              const int4* __restrict__ dst4,
                                              const float4* __restrict__ ew4) {
    int i0 = blockIdx.x * blockDim.x + threadIdx.x;   // always < NQ
    int i1 = i0 + ESTRIDE;
    bool a1 = i1 < NQ;
    int4   s0 = __ldg(&src4[i0]);
    int4   d0 = __ldg(&dst4[i0]);
    float4 w0 = __ldg(&ew4[i0]);
    int4 s1, d1; float4 w1;
    if (a1) { s1 = __ldg(&src4[i1]); d1 = __ldg(&dst4[i1]); w1 = __ldg(&ew4[i1]); }
    cudaGridDependencySynchronize();
    float2 h0 = g_hhd[s0.x], h1 = g_hhd[s0.y], h2 = g_hhd[s0.z], h3 = g_hhd[s0.w];
    atomicAdd(&g_u[d0.x], make_float2(h0.x * w0.x, h0.y * w0.x));
    atomicAdd(&g_u[d0.y], make_float2(h1.x * w0.y, h1.y * w0.y));
    atomicAdd(&g_u[d0.z], make_float2(h2.x * w0.z, h2.y * w0.z));
    atomicAdd(&g_u[d0.w], make_float2(h3.x * w0.w, h3.y * w0.w));
    if (a1) {
        float2 h4 = g_hhd[s1.x], h5 = g_hhd[s1.y], h6 = g_hhd[s1.z], h7 = g_hhd[s1.w];
        atomicAdd(&g_u[d1.x], make_float2(h4.x * w1.x, h4.y * w1.x));
        atomicAdd(&g_u[d1.y], make_float2(h5.x * w1.y, h5.y * w1.y));
        atomicAdd(&g_u[d1.z], make_float2(h6.x * w1.z, h6.y * w1.z));
        atomicAdd(&g_u[d1.w], make_float2(h7.x * w1.w, h7.y * w1.w));
    }
}

// K7: pool out2[n] = dinv[n]*(u[n] + hhd[n]) + counts (warp-aggregated),
//     last block finalizes output and self-cleans pool state.
__global__ void k_pool(const int* __restrict__ batch, const float* __restrict__ b2,
                       float* __restrict__ out, int nblocks) {
    int tid = threadIdx.x;
    int n = blockIdx.x * blockDim.x + tid;
    bool valid = n < N_NODES;
    int g = 0;
    if (valid) g = __ldg(&batch[n]);     // pure input, prefetch pre-sync
    cudaGridDependencySynchronize();
    float vx = 0.f, vy = 0.f, c = 0.f;
    if (valid) {
        float di = g_dinv[n];
        float2 u = g_u[n];
        float2 h = g_hhd[n];
        vx = (u.x + h.x) * di; vy = (u.y + h.y) * di; c = 1.f;
    }
    // batch is sorted: warps almost always graph-uniform; lane 0 valid if any lane is
    int g0 = __shfl_sync(0xffffffffu, g, 0);
    bool uni = __all_sync(0xffffffffu, (g == g0) || !valid);
    if (uni) {
#pragma unroll
        for (int o = 16; o; o >>= 1) {
            vx += __shfl_down_sync(0xffffffffu, vx, o);
            vy += __shfl_down_sync(0xffffffffu, vy, o);
            c  += __shfl_down_sync(0xffffffffu, c,  o);
        }
        if ((tid & 31) == 0 && c > 0.f) {
            atomicAdd(&g_pool[g0 * 2 + 0], vx);
            atomicAdd(&g_pool[g0 * 2 + 1], vy);
            atomicAdd(&g_cnt[g0], c);
        }
    } else if (valid) {
        atomicAdd(&g_pool[g * 2 + 0], vx);
        atomicAdd(&g_pool[g * 2 + 1], vy);
        atomicAdd(&g_cnt[g], 1.0f);
    }
    // last-block finalize + self-clean
    __shared__ bool last;
    __threadfence();
    __syncthreads();
    if (tid == 0) last = (atomicAdd(&g_done, 1u) == (unsigned)(nblocks - 1));
    __syncthreads();
    if (last) {
        if (tid < N_GRAPHS) {
            float cc = fmaxf(g_cnt[tid], 1.0f);
            out[tid * 2 + 0] = g_pool[tid * 2 + 0] / cc + __ldg(&b2[0]);
            out[tid * 2 + 1] = g_pool[tid * 2 + 1] / cc + __ldg(&b2[1]);
            g_pool[tid * 2 + 0] = 0.0f;
            g_pool[tid * 2 + 1] = 0.0f;
            g_cnt[tid] = 0.0f;
        }
        if (tid == 0) g_done = 0u;
    }
}

// ---- PDL launcher: overlap each kernel's ramp with predecessor's tail ----
static void launch_pdl(const void* func, int grid, int block, void** args) {
    cudaLaunchConfig_t cfg = {};
    cfg.gridDim  = dim3(grid, 1, 1);
    cfg.blockDim = dim3(block, 1, 1);
    cudaLaunchAttribute attr[1];
    attr[0].id = cudaLaunchAttributeProgrammaticStreamSerialization;
    attr[0].val.programmaticStreamSerializationAllowed = 1;
    cfg.attrs = attr;
    cfg.numAttrs = 1;
    cudaLaunchKernelExC(&cfg, func, args);
}

extern "C" void kernel_launch(void* const* d_in, const int* in_sizes, int n_in,
                              void* d_out, int out_size) {
    const float* x     = (const float*)d_in[0];
    const int*   ei    = (const int*)  d_in[1];   // [2, E]
    const float* ew    = (const float*)d_in[2];
    const int*   batch = (const int*)  d_in[3];
    const float* W1    = (const float*)d_in[4];
    const float* gamma = (const float*)d_in[6];
    const float* beta  = (const float*)d_in[7];
    const float* W2    = (const float*)d_in[8];
    const float* b2    = (const float*)d_in[9];
    float* out = (float*)d_out;

    const int4*   src4 = (const int4*)  ei;
    const int4*   dst4 = (const int4*) (ei + N_EDGES);
    const float4* ew4  = (const float4*) ew;

    const int BT  = 256;
    const int GN  = (N_NODES + BT - 1) / BT;
    const int GR  = (NN2 + 255) / 256;

    { void* a[] = { (void*)&dst4, (void*)&ew4 };
      launch_pdl((const void*)k_deg, EBLOCKS, BT, a); }
    { void* a[] = { (void*)&x };
      launch_pdl((const void*)k_dinv, GN, BT, a); }
    { void* a[] = { (void*)&src4, (void*)&dst4, (void*)&ew4 };
      launch_pdl((const void*)k_agg1, EBLOCKS, BT, a); }
    launch_pdl((const void*)k_reduce, GR, 256, nullptr);
    { void* a[] = { (void*)&W1, (void*)&gamma, (void*)&beta, (void*)&W2 };
      launch_pdl((const void*)k_hh, GN, BT, a); }
    { void* a[] = { (void*)&src4, (void*)&dst4, (void*)&ew4 };
      launch_pdl((const void*)k_agg2, EBLOCKS, BT, a); }
    { int gn = GN;
      void* a[] = { (void*)&batch, (void*)&b2, (void*)&out, (void*)&gn };
      launch_pdl((const void*)k_pool, GN, BT, a); }
}